// round 11
// baseline (speedup 1.0000x reference)
#include <cuda_runtime.h>
#include <cuda_bf16.h>
#include <math.h>
#include <cstdint>

// Problem constants
#define FL        256
#define NSC       32
#define SIG_LEN   65536
#define BATCH     16
#define HALF      128

// GEMM tiling: CTA = 128 t-positions (8 warps x 16 rows), N = 64 (32 scales
// x re/im), K = 3 x 256 (bf16 split segments).
#define TILE_M    128
#define THREADS   256
#define WIN       384      // signal window per CTA: 128 + 256

// Wavelet bank, k-major [n][tap], n = 2*scale + (0=re,1=im).
__device__ __align__(16) __nv_bfloat16 g_Bh[64][256];  // high bf16 part
__device__ __align__(16) __nv_bfloat16 g_Bl[64][256];  // low  bf16 part
__device__ int g_dtype_flag;

// ---------------------------------------------------------------------------
// Init: wavelet bank in fp64, split into bf16 high/low parts.
// ---------------------------------------------------------------------------
__global__ void winit_kernel() {
    int idx = blockIdx.x * blockDim.x + threadIdx.x;
    if (idx >= 64 * 256) return;
    int n = idx >> 8;
    int k = idx & 255;
    int s  = n >> 1;
    int ri = n & 1;
    double scale = (double)(s + 1);
    double t   = ((double)k - 128.0) / scale;
    double env = exp(-0.5 * t * t);
    double ph  = (2.0 * 3.14159265358979323846 * 6.0) * t / scale;
    float wf = (float)(env * (ri ? sin(ph) : cos(ph)));
    __nv_bfloat16 wh = __float2bfloat16(wf);
    __nv_bfloat16 wl = __float2bfloat16(wf - __bfloat162float(wh));
    g_Bh[n][k] = wh;
    g_Bl[n][k] = wl;
}

// ---------------------------------------------------------------------------
// Probe (parallel): input dtype from the first 4KB only. 0=bf16, 1=fp32.
// ---------------------------------------------------------------------------
__global__ void dtype_probe_kernel(const void* sig) {
    __shared__ int s_crazy;
    if (threadIdx.x == 0) s_crazy = 0;
    __syncthreads();
    const __nv_bfloat16* p = (const __nv_bfloat16*)sig;
    int crazy = 0;
#pragma unroll
    for (int j = 0; j < 8; j++) {
        float v = __bfloat162float(p[threadIdx.x * 8 + j]);
        float a = fabsf(v);
        if (v != v) crazy++;
        else if (a != 0.0f && (a > 64.0f || a < 9.5367431640625e-7f)) crazy++;
    }
    for (int off = 16; off > 0; off >>= 1)
        crazy += __shfl_down_sync(0xffffffffu, crazy, off);
    if ((threadIdx.x & 31) == 0) atomicAdd(&s_crazy, crazy);
    __syncthreads();
    if (threadIdx.x == 0) g_dtype_flag = (s_crazy > 200) ? 1 : 0;
}

// ---------------------------------------------------------------------------
// m16n8k16 bf16 MMA (baseline PTX; executes as HMMA on sm_103).
// ---------------------------------------------------------------------------
__device__ __forceinline__ void mma16816(float& c0, float& c1, float& c2, float& c3,
                                         uint32_t a0, uint32_t a1, uint32_t a2,
                                         uint32_t a3, uint32_t b0, uint32_t b1) {
    asm volatile(
        "mma.sync.aligned.m16n8k16.row.col.f32.bf16.bf16.f32 "
        "{%0,%1,%2,%3}, {%4,%5,%6,%7}, {%8,%9}, {%0,%1,%2,%3};"
        : "+f"(c0), "+f"(c1), "+f"(c2), "+f"(c3)
        : "r"(a0), "r"(a1), "r"(a2), "r"(a3), "r"(b0), "r"(b1));
}
__device__ __forceinline__ uint32_t packh(unsigned short lo, unsigned short hi) {
    return (uint32_t)lo | ((uint32_t)hi << 16);
}

// ---------------------------------------------------------------------------
// Main kernel. Warp w handles rows t = tile0 + 16w .. +16; the full N=64 via
// 8 n-tiles of width 8; K = 3 segments x 256 taps, k-step 16.
// A is Hankel: A[t][k] = win[t + k]  ->  fragment needs only 3 distinct pairs.
// ---------------------------------------------------------------------------
__global__ void __launch_bounds__(THREADS)
morlet_mma_kernel(const void* __restrict__ sig_raw, float* __restrict__ outf,
                  long long n_sig, long long w_floats, int mode) {
    __shared__ __nv_bfloat16 s_xh[WIN];
    __shared__ __nv_bfloat16 s_xl[WIN];

    const int tid  = threadIdx.x;
    const int b     = blockIdx.y;
    const int tile0 = blockIdx.x * TILE_M;
    const int dtype = g_dtype_flag;

    // Stage window: win[i] = x[tile0 - 128 + i], bf16-split, fully guarded.
    {
        const long long sbase = (long long)b * SIG_LEN;
        const float*         sigf = (const float*)sig_raw;
        const __nv_bfloat16* sigb = (const __nv_bfloat16*)sig_raw;
        for (int i = tid; i < WIN; i += THREADS) {
            int gl = tile0 - HALF + i;
            long long g = sbase + gl;
            float v = 0.0f;
            if (gl >= 0 && gl < SIG_LEN && g >= 0 && g < n_sig)
                v = dtype ? sigf[g] : __bfloat162float(sigb[g]);
            __nv_bfloat16 h = __float2bfloat16(v);
            s_xh[i] = h;
            s_xl[i] = __float2bfloat16(v - __bfloat162float(h));
        }
    }
    __syncthreads();

    const int warp = tid >> 5;
    const int lane = tid & 31;
    const int g  = lane >> 2;       // 0..7  (row group)
    const int tq = lane & 3;        // 0..3  (col group)
    const int W  = warp * 16;       // warp's first t-row

    // Accumulators: 8 n-tiles x 4 fp32.
    float acc[8][4];
#pragma unroll
    for (int j = 0; j < 8; j++)
#pragma unroll
        for (int q = 0; q < 4; q++) acc[j][q] = 0.0f;

#pragma unroll
    for (int seg = 0; seg < 3; seg++) {
        const __nv_bfloat16* win = (seg == 1) ? s_xl : s_xh;
        const __nv_bfloat16* Bm  = (seg == 2) ? &g_Bl[0][0] : &g_Bh[0][0];

        for (int k0 = 0; k0 < 256; k0 += 16) {
            // Envelope truncation: skip n-tiles j with all |tap-128| > 7*(4j+4).
            int lo = k0 - 128, hi = k0 + 15 - 128;
            int mind = (lo > 0) ? lo : ((hi < 0) ? -hi : 0);
            int jmin = (mind <= 28) ? 0 : ((mind - 1) / 28);
            if (jmin >= 8) continue;

            // A fragment via Hankel collapse: pairs at base, base+8, base+16.
            const int abase = W + g + k0 + 2 * tq;
            const unsigned short* wh = (const unsigned short*)win;
            uint32_t P0 = packh(wh[abase],      wh[abase + 1]);
            uint32_t P1 = packh(wh[abase + 8],  wh[abase + 9]);
            uint32_t P2 = packh(wh[abase + 16], wh[abase + 17]);
            // a0 = A[g][2t,2t+1], a1 = A[g+8][...] = P1 (Hankel), a2 = cols+8
            // = P1, a3 = P2.

            const int kb = k0 + 2 * tq;     // even -> 4B-aligned u32 loads
#pragma unroll
            for (int j = 0; j < 8; j++) {
                if (j < jmin) continue;
                const int n = 8 * j + g;
                const uint32_t* bp = (const uint32_t*)(Bm + n * 256 + kb);
                uint32_t b0 = __ldg(bp);        // taps kb, kb+1
                uint32_t b1 = __ldg(bp + 4);    // taps kb+8, kb+9
                mma16816(acc[j][0], acc[j][1], acc[j][2], acc[j][3],
                         P0, P1, P1, P2, b0, b1);
            }
        }
    }

    // Epilogue: D cols (2t, 2t+1) are (re, im) of scale s = 4j + tq.
    // c0/c1 -> row g; c2/c3 -> row g+8.
    const int t0 = tile0 + W + g;
#pragma unroll
    for (int j = 0; j < 8; j++) {
        const int s = 4 * j + tq;
        long long cIdx0 = ((long long)(b * NSC + s)) * SIG_LEN + t0;
        if (mode) {
            long long f0 = 2 * cIdx0;
            if (f0 + 1 < w_floats)
                *(float2*)(outf + f0) = make_float2(acc[j][0], acc[j][1]);
            long long f1 = f0 + 16;               // row g+8: t0+8 -> +16 floats
            if (f1 + 1 < w_floats)
                *(float2*)(outf + f1) = make_float2(acc[j][2], acc[j][3]);
        } else {
            if (cIdx0 < w_floats)     outf[cIdx0]     = acc[j][0];
            if (cIdx0 + 8 < w_floats) outf[cIdx0 + 8] = acc[j][2];
        }
    }
}

// ---------------------------------------------------------------------------
// Launch contract. Output treated as out_size FLOATS -> no overrun possible.
// ---------------------------------------------------------------------------
extern "C" void kernel_launch(void* const* d_in, const int* in_sizes, int n_in,
                              void* d_out, int out_size) {
    const void* sig = d_in[0];
    float* outf = (float*)d_out;

    long long n_sig = (long long)in_sizes[0];
    long long structural_sig = (long long)BATCH * SIG_LEN;
    if (structural_sig < n_sig) n_sig = structural_sig;

    long long w_floats = (long long)out_size;
    long long need_interleaved = 2LL * BATCH * NSC * SIG_LEN;  // 67,108,864
    int mode = (w_floats >= need_interleaved) ? 1 : 0;

    winit_kernel<<<(64 * 256 + 255) / 256, 256>>>();
    dtype_probe_kernel<<<1, 256>>>(sig);

    dim3 grid(SIG_LEN / TILE_M, BATCH);
    morlet_mma_kernel<<<grid, THREADS>>>(sig, outf, n_sig, w_floats, mode);
}

// round 12
// speedup vs baseline: 3.8365x; 3.8365x over previous
#include <cuda_runtime.h>
#include <cuda_bf16.h>
#include <math.h>

// Problem constants
#define FL        256
#define NSC       32
#define SIG_LEN   65536
#define BATCH     16
#define HALF      128

// Tiling: block = (2048-t tile, batch, scale-group-of-4)
#define TILE_T    2048
#define NT        8
#define NS        4
#define BLOCK_THREADS 256   // 8 warps; warp w covers t [w*256, (w+1)*256)
#define WIN       (TILE_T + FL)   // 2304

// Input dtype flag: 0 = bf16, 1 = float32.
__device__ int g_dtype_flag;

__global__ void dtype_probe_kernel(const void* sig) {
    __shared__ int s_crazy;
    if (threadIdx.x == 0) s_crazy = 0;
    __syncthreads();
    const __nv_bfloat16* p = (const __nv_bfloat16*)sig;
    int crazy = 0;
#pragma unroll
    for (int j = 0; j < 8; j++) {
        float v = __bfloat162float(p[threadIdx.x * 8 + j]);
        float a = fabsf(v);
        if (v != v) crazy++;
        else if (a != 0.0f && (a > 64.0f || a < 9.5367431640625e-7f)) crazy++;
    }
    for (int off = 16; off > 0; off >>= 1)
        crazy += __shfl_down_sync(0xffffffffu, crazy, off);
    if ((threadIdx.x & 31) == 0) atomicAdd(&s_crazy, crazy);
    __syncthreads();
    if (threadIdx.x == 0) g_dtype_flag = (s_crazy > 200) ? 1 : 0;
}

// Packed f32x2 helpers: low = real, high = imag.
__device__ __forceinline__ unsigned long long pack_dup(float x) {
    unsigned long long r;
    asm("mov.b64 %0, {%1, %1};" : "=l"(r) : "r"(__float_as_uint(x)));
    return r;
}
__device__ __forceinline__ unsigned long long pack2(float lo, float hi) {
    unsigned long long r;
    asm("mov.b64 %0, {%1, %2};" : "=l"(r)
        : "r"(__float_as_uint(lo)), "r"(__float_as_uint(hi)));
    return r;
}
__device__ __forceinline__ unsigned long long ffma2(unsigned long long a,
                                                    unsigned long long b,
                                                    unsigned long long c) {
    unsigned long long d;
    asm("fma.rn.f32x2 %0, %1, %2, %3;" : "=l"(d) : "l"(a), "l"(b), "l"(c));
    return d;
}

// ---------------------------------------------------------------------------
// Symmetry-folded kernel. wr even / wi odd around k=128:
//   pair k=128±d:  acc += ffma2((wr,wi), (xp+xm, xp-xm))
// One FFMA2 covers TWO taps for all 4 scales. Coef table holds +d side only.
// ---------------------------------------------------------------------------
__global__ void __launch_bounds__(BLOCK_THREADS)
morlet_kernel(const void* __restrict__ sig_raw, float* __restrict__ outf,
              long long n_sig, long long w_floats, int mode) {
    __shared__ __align__(16) float  s_sig[WIN];       // 9 KB
    __shared__ __align__(16) float2 s_wav[128][NS];   // 4 KB, d = 0..127

    const int b     = blockIdx.y;
    const int tile0 = blockIdx.x * TILE_T;
    const int grp   = blockIdx.z;
    const int s0    = grp * NS;
    const long long sbase = (long long)b * SIG_LEN;
    const int dtype = g_dtype_flag;

    const float*          sigf = (const float*)sig_raw;
    const __nv_bfloat16*  sigb = (const __nv_bfloat16*)sig_raw;

    // Stage signal window (zero-padded, guarded).
    for (int i = threadIdx.x; i < WIN; i += BLOCK_THREADS) {
        int gl = tile0 - HALF + i;
        long long g = sbase + gl;
        float v = 0.0f;
        if (gl >= 0 && gl < SIG_LEN && g >= 0 && g < n_sig)
            v = dtype ? sigf[g] : __bfloat162float(sigb[g]);
        s_sig[i] = v;
    }

    // Coef table: w(k=128+d) for d=0..127, this group's 4 scales.
    const float TWO_PI_OSC = 37.69911184307752f;  // 2*pi*6
#pragma unroll
    for (int j = 0; j < 2; j++) {
        int ci = threadIdx.x * 2 + j;    // 0..511
        int d  = ci >> 2;
        int si = ci & 3;
        float scale = (float)(s0 + si + 1);
        float t   = (float)d / scale;
        float env = expf(-0.5f * t * t);
        float ph  = TWO_PI_OSC * t / scale;
        float sn, cs;
        sincosf(ph, &sn, &cs);
        s_wav[d][si] = make_float2(env * cs, env * sn);
    }
    __syncthreads();

    const int lane = threadIdx.x & 31;
    const int wrp  = threadIdx.x >> 5;
    const int tloc = wrp * 256 + lane * NT;       // multiple of 8

    // d-range: r_d = 7 * scale_max, capped 127 (k=0 tap dropped: env<=3.3e-4).
    const int scale_max = s0 + NS;
    int r_d = 7 * scale_max;
    if (r_d > 127) r_d = 127;
    const int mmax = r_d >> 2;

    unsigned long long acc[NS][NT];
#pragma unroll
    for (int si = 0; si < NS; si++)
#pragma unroll
        for (int tt = 0; tt < NT; tt++) acc[si][tt] = 0ull;

    // ---- m = 0 chunk (d = 0..3): center tap at dk=0 handled specially ----
    {
        const float4 p0 = *(const float4*)&s_sig[tloc + 128];
        const float4 p1 = *(const float4*)&s_sig[tloc + 132];
        const float4 p2 = *(const float4*)&s_sig[tloc + 136];
        const float4 q0 = *(const float4*)&s_sig[tloc + 124];
        const float4 q1 = *(const float4*)&s_sig[tloc + 128];
        const float4 q2 = *(const float4*)&s_sig[tloc + 132];
        float xp[12] = {p0.x,p0.y,p0.z,p0.w, p1.x,p1.y,p1.z,p1.w, p2.x,p2.y,p2.z,p2.w};
        float xm[12] = {q0.x,q0.y,q0.z,q0.w, q1.x,q1.y,q1.z,q1.w, q2.x,q2.y,q2.z,q2.w};

        // dk = 0: center, u = (x, x); wi[0] = 0 exactly so im untouched.
        {
            ulonglong2 c01 = *(const ulonglong2*)&s_wav[0][0];
            ulonglong2 c23 = *(const ulonglong2*)&s_wav[0][2];
            unsigned long long wq[NS] = {c01.x, c01.y, c23.x, c23.y};
#pragma unroll
            for (int tt = 0; tt < NT; tt++) {
                unsigned long long u = pack_dup(xp[tt]);
#pragma unroll
                for (int si = 0; si < NS; si++)
                    acc[si][tt] = ffma2(wq[si], u, acc[si][tt]);
            }
        }
#pragma unroll
        for (int dk = 1; dk < 4; dk++) {
            ulonglong2 c01 = *(const ulonglong2*)&s_wav[dk][0];
            ulonglong2 c23 = *(const ulonglong2*)&s_wav[dk][2];
            unsigned long long wq[NS] = {c01.x, c01.y, c23.x, c23.y};
#pragma unroll
            for (int tt = 0; tt < NT; tt++) {
                float a = xp[dk + tt], m = xm[4 - dk + tt];
                unsigned long long u = pack2(a + m, a - m);
#pragma unroll
                for (int si = 0; si < NS; si++)
                    acc[si][tt] = ffma2(wq[si], u, acc[si][tt]);
            }
        }
    }

    // ---- main chunks m = 1..mmax (d = 4m..4m+3) ----
    for (int m = 1; m <= mmax; m++) {
        const int pb = tloc + 128 + 4 * m;
        const int qb = tloc + 124 - 4 * m;
        const float4 p0 = *(const float4*)&s_sig[pb];
        const float4 p1 = *(const float4*)&s_sig[pb + 4];
        const float4 p2 = *(const float4*)&s_sig[pb + 8];
        const float4 q0 = *(const float4*)&s_sig[qb];
        const float4 q1 = *(const float4*)&s_sig[qb + 4];
        const float4 q2 = *(const float4*)&s_sig[qb + 8];
        float xp[12] = {p0.x,p0.y,p0.z,p0.w, p1.x,p1.y,p1.z,p1.w, p2.x,p2.y,p2.z,p2.w};
        float xm[12] = {q0.x,q0.y,q0.z,q0.w, q1.x,q1.y,q1.z,q1.w, q2.x,q2.y,q2.z,q2.w};

#pragma unroll
        for (int dk = 0; dk < 4; dk++) {
            const int d = 4 * m + dk;
            ulonglong2 c01 = *(const ulonglong2*)&s_wav[d][0];
            ulonglong2 c23 = *(const ulonglong2*)&s_wav[d][2];
            unsigned long long wq[NS] = {c01.x, c01.y, c23.x, c23.y};
#pragma unroll
            for (int tt = 0; tt < NT; tt++) {
                float a = xp[dk + tt], mm = xm[4 - dk + tt];
                unsigned long long u = pack2(a + mm, a - mm);
#pragma unroll
                for (int si = 0; si < NS; si++)
                    acc[si][tt] = ffma2(wq[si], u, acc[si][tt]);
            }
        }
    }

    // Store. Complex position c = ((b*NSC + s)*SIG_LEN + t).
    const int tglob = tile0 + tloc;
#pragma unroll
    for (int si = 0; si < NS; si++) {
        long long cbase = ((long long)(b * NSC + s0 + si)) * SIG_LEN + tglob;
#pragma unroll
        for (int tt = 0; tt < NT; tt++) {
            long long c = cbase + tt;
            float re = __uint_as_float((unsigned)(acc[si][tt] & 0xffffffffull));
            float im = __uint_as_float((unsigned)(acc[si][tt] >> 32));
            if (mode) {
                long long f = 2 * c;
                if (f + 1 < w_floats)
                    *(float2*)(outf + f) = make_float2(re, im);
            } else {
                if (c < w_floats) outf[c] = re;
            }
        }
    }
}

// ---------------------------------------------------------------------------
// Launch contract. Output treated as out_size FLOATS -> no overrun possible.
// ---------------------------------------------------------------------------
extern "C" void kernel_launch(void* const* d_in, const int* in_sizes, int n_in,
                              void* d_out, int out_size) {
    const void* sig = d_in[0];
    float* outf = (float*)d_out;

    long long n_sig = (long long)in_sizes[0];
    long long structural_sig = (long long)BATCH * SIG_LEN;
    if (structural_sig < n_sig) n_sig = structural_sig;

    long long w_floats = (long long)out_size;
    long long need_interleaved = 2LL * BATCH * NSC * SIG_LEN;
    int mode = (w_floats >= need_interleaved) ? 1 : 0;

    dtype_probe_kernel<<<1, 256>>>(sig);

    dim3 grid(SIG_LEN / TILE_T, BATCH, NSC / NS);   // (32, 16, 8)
    morlet_kernel<<<grid, BLOCK_THREADS>>>(sig, outf, n_sig, w_floats, mode);
}

// round 13
// speedup vs baseline: 3.8799x; 1.0113x over previous
#include <cuda_runtime.h>
#include <cuda_bf16.h>
#include <math.h>

// Problem constants
#define FL        256
#define NSC       32
#define SIG_LEN   65536
#define BATCH     16
#define HALF      128

// Tiling: block = (1024-t tile, batch, scale-group-of-8)
#define TILE_T    1024
#define NT        4
#define NS        8
#define BLOCK_THREADS 256   // 8 warps; warp w covers t [w*128, (w+1)*128)
#define WIN       (TILE_T + FL)   // 1280

// Input dtype flag: 0 = bf16, 1 = float32.
__device__ int g_dtype_flag;

__global__ void dtype_probe_kernel(const void* sig) {
    __shared__ int s_crazy;
    if (threadIdx.x == 0) s_crazy = 0;
    __syncthreads();
    const __nv_bfloat16* p = (const __nv_bfloat16*)sig;
    int crazy = 0;
#pragma unroll
    for (int j = 0; j < 8; j++) {
        float v = __bfloat162float(p[threadIdx.x * 8 + j]);
        float a = fabsf(v);
        if (v != v) crazy++;
        else if (a != 0.0f && (a > 64.0f || a < 9.5367431640625e-7f)) crazy++;
    }
    for (int off = 16; off > 0; off >>= 1)
        crazy += __shfl_down_sync(0xffffffffu, crazy, off);
    if ((threadIdx.x & 31) == 0) atomicAdd(&s_crazy, crazy);
    __syncthreads();
    if (threadIdx.x == 0) g_dtype_flag = (s_crazy > 200) ? 1 : 0;
}

// Packed f32x2 helpers: low = real, high = imag.
__device__ __forceinline__ unsigned long long pack_dup(float x) {
    unsigned long long r;
    asm("mov.b64 %0, {%1, %1};" : "=l"(r) : "r"(__float_as_uint(x)));
    return r;
}
__device__ __forceinline__ unsigned long long pack2(float lo, float hi) {
    unsigned long long r;
    asm("mov.b64 %0, {%1, %2};" : "=l"(r)
        : "r"(__float_as_uint(lo)), "r"(__float_as_uint(hi)));
    return r;
}
__device__ __forceinline__ unsigned long long ffma2(unsigned long long a,
                                                    unsigned long long b,
                                                    unsigned long long c) {
    unsigned long long d;
    asm("fma.rn.f32x2 %0, %1, %2, %3;" : "=l"(d) : "l"(a), "l"(b), "l"(c));
    return d;
}

// ---------------------------------------------------------------------------
// Symmetry-folded kernel, NS=8 scales/block (amortizes the sum/diff FADDs),
// sliding register window for the signal (1 float4 load per side per chunk).
//   pair k=128±d:  acc += ffma2((wr,wi), (xp+xm, xp-xm))
// ---------------------------------------------------------------------------
__global__ void __launch_bounds__(BLOCK_THREADS)
morlet_kernel(const void* __restrict__ sig_raw, float* __restrict__ outf,
              long long n_sig, long long w_floats, int mode) {
    __shared__ __align__(16) float  s_sig[WIN];       // 5 KB
    __shared__ __align__(16) float2 s_wav[128][NS];   // 8 KB, d = 0..127

    const int b     = blockIdx.y;
    const int tile0 = blockIdx.x * TILE_T;
    const int grp   = blockIdx.z;        // 0..3
    const int s0    = grp * NS;
    const long long sbase = (long long)b * SIG_LEN;
    const int dtype = g_dtype_flag;

    const float*          sigf = (const float*)sig_raw;
    const __nv_bfloat16*  sigb = (const __nv_bfloat16*)sig_raw;

    // Stage signal window (zero-padded, guarded).
    for (int i = threadIdx.x; i < WIN; i += BLOCK_THREADS) {
        int gl = tile0 - HALF + i;
        long long g = sbase + gl;
        float v = 0.0f;
        if (gl >= 0 && gl < SIG_LEN && g >= 0 && g < n_sig)
            v = dtype ? sigf[g] : __bfloat162float(sigb[g]);
        s_sig[i] = v;
    }

    // Coef table: w(k=128+d) for d = 0..127, 8 scales. 1024 entries, 4/thread.
    const float TWO_PI_OSC = 37.69911184307752f;  // 2*pi*6
#pragma unroll
    for (int j = 0; j < 4; j++) {
        int ci = threadIdx.x * 4 + j;    // 0..1023
        int d  = ci >> 3;
        int si = ci & 7;
        float scale = (float)(s0 + si + 1);
        float t   = (float)d / scale;
        float env = expf(-0.5f * t * t);
        float ph  = TWO_PI_OSC * t / scale;
        float sn, cs;
        sincosf(ph, &sn, &cs);
        s_wav[d][si] = make_float2(env * cs, env * sn);
    }
    __syncthreads();

    const int lane = threadIdx.x & 31;
    const int wrp  = threadIdx.x >> 5;
    const int tloc = wrp * 128 + lane * NT;       // multiple of 4

    // d-range: r_d = 7 * scale_max, capped 127 (k=0 tap dropped, env<=3.3e-4).
    const int scale_max = s0 + NS;
    int r_d = 7 * scale_max;
    if (r_d > 127) r_d = 127;
    const int mmax = r_d >> 2;

    // Packed accumulators: (re, im) per (scale, t).
    unsigned long long acc[NS][NT];
#pragma unroll
    for (int si = 0; si < NS; si++)
#pragma unroll
        for (int tt = 0; tt < NT; tt++) acc[si][tt] = 0ull;

    // Sliding windows: xp covers s_sig[tloc+128+4m .. +8), xm covers
    // s_sig[tloc+124-4m .. +8). Indices used: xp[dk+tt] (0..6), xm[4-dk+tt] (1..7).
    float xp[8], xm[8];
    {
        const float4 p0 = *(const float4*)&s_sig[tloc + 128];
        const float4 p1 = *(const float4*)&s_sig[tloc + 132];
        const float4 q0 = *(const float4*)&s_sig[tloc + 124];
        const float4 q1 = *(const float4*)&s_sig[tloc + 128];
        xp[0]=p0.x; xp[1]=p0.y; xp[2]=p0.z; xp[3]=p0.w;
        xp[4]=p1.x; xp[5]=p1.y; xp[6]=p1.z; xp[7]=p1.w;
        xm[0]=q0.x; xm[1]=q0.y; xm[2]=q0.z; xm[3]=q0.w;
        xm[4]=q1.x; xm[5]=q1.y; xm[6]=q1.z; xm[7]=q1.w;
    }

    // Per-(dk): load 8 packed coefs (4 broadcast LDS.128), apply to 4 t.
    auto tap = [&](int d, int dk) {
        ulonglong2 c01 = *(const ulonglong2*)&s_wav[d][0];
        ulonglong2 c23 = *(const ulonglong2*)&s_wav[d][2];
        ulonglong2 c45 = *(const ulonglong2*)&s_wav[d][4];
        ulonglong2 c67 = *(const ulonglong2*)&s_wav[d][6];
        unsigned long long wq[NS] = {c01.x, c01.y, c23.x, c23.y,
                                     c45.x, c45.y, c67.x, c67.y};
#pragma unroll
        for (int tt = 0; tt < NT; tt++) {
            float a = xp[dk + tt], m = xm[4 - dk + tt];
            unsigned long long u = pack2(a + m, a - m);
#pragma unroll
            for (int si = 0; si < NS; si++)
                acc[si][tt] = ffma2(wq[si], u, acc[si][tt]);
        }
    };

    // ---- m = 0: center tap (d=0) uses u=(x,x); wi[0]=0 exactly ----
    {
        ulonglong2 c01 = *(const ulonglong2*)&s_wav[0][0];
        ulonglong2 c23 = *(const ulonglong2*)&s_wav[0][2];
        ulonglong2 c45 = *(const ulonglong2*)&s_wav[0][4];
        ulonglong2 c67 = *(const ulonglong2*)&s_wav[0][6];
        unsigned long long wq[NS] = {c01.x, c01.y, c23.x, c23.y,
                                     c45.x, c45.y, c67.x, c67.y};
#pragma unroll
        for (int tt = 0; tt < NT; tt++) {
            unsigned long long u = pack_dup(xp[tt]);
#pragma unroll
            for (int si = 0; si < NS; si++)
                acc[si][tt] = ffma2(wq[si], u, acc[si][tt]);
        }
        tap(1, 1); tap(2, 2); tap(3, 3);
    }

    // ---- m = 1..mmax: slide windows, then 4 taps ----
    for (int m = 1; m <= mmax; m++) {
        // xp: shift left by 4, load new high float4 at tloc+128+4m+4.
        xp[0] = xp[4]; xp[1] = xp[5]; xp[2] = xp[6]; xp[3] = xp[7];
        {
            const float4 pn = *(const float4*)&s_sig[tloc + 132 + 4 * m];
            xp[4] = pn.x; xp[5] = pn.y; xp[6] = pn.z; xp[7] = pn.w;
        }
        // xm: shift right by 4, load new low float4 at tloc+124-4m.
        xm[4] = xm[0]; xm[5] = xm[1]; xm[6] = xm[2]; xm[7] = xm[3];
        {
            const float4 qn = *(const float4*)&s_sig[tloc + 124 - 4 * m];
            xm[0] = qn.x; xm[1] = qn.y; xm[2] = qn.z; xm[3] = qn.w;
        }
        const int d0 = 4 * m;
        tap(d0, 0); tap(d0 + 1, 1); tap(d0 + 2, 2); tap(d0 + 3, 3);
    }

    // Store: 2 float4 per scale (4 t = 4 float2, 16B-aligned pairs).
    const int tglob = tile0 + tloc;
#pragma unroll
    for (int si = 0; si < NS; si++) {
        long long cbase = ((long long)(b * NSC + s0 + si)) * SIG_LEN + tglob;
#pragma unroll
        for (int tt = 0; tt < NT; tt++) {
            long long c = cbase + tt;
            float re = __uint_as_float((unsigned)(acc[si][tt] & 0xffffffffull));
            float im = __uint_as_float((unsigned)(acc[si][tt] >> 32));
            if (mode) {
                long long f = 2 * c;
                if (f + 1 < w_floats)
                    *(float2*)(outf + f) = make_float2(re, im);
            } else {
                if (c < w_floats) outf[c] = re;
            }
        }
    }
}

// ---------------------------------------------------------------------------
// Launch contract. Output treated as out_size FLOATS -> no overrun possible.
// ---------------------------------------------------------------------------
extern "C" void kernel_launch(void* const* d_in, const int* in_sizes, int n_in,
                              void* d_out, int out_size) {
    const void* sig = d_in[0];
    float* outf = (float*)d_out;

    long long n_sig = (long long)in_sizes[0];
    long long structural_sig = (long long)BATCH * SIG_LEN;
    if (structural_sig < n_sig) n_sig = structural_sig;

    long long w_floats = (long long)out_size;
    long long need_interleaved = 2LL * BATCH * NSC * SIG_LEN;
    int mode = (w_floats >= need_interleaved) ? 1 : 0;

    dtype_probe_kernel<<<1, 256>>>(sig);

    dim3 grid(SIG_LEN / TILE_T, BATCH, NSC / NS);   // (64, 16, 4)
    morlet_kernel<<<grid, BLOCK_THREADS>>>(sig, outf, n_sig, w_floats, mode);
}